// round 1
// baseline (speedup 1.0000x reference)
#include <cuda_runtime.h>
#include <cstdint>

// LIF neuron scan: v = 0.5*v + x_t; spike = (v >= 1); v = spike ? 0 : v
// x: [T, B, D] f32, v0: [D] f32, out spikes: [T, B, D] f32.
// Each thread owns one float4 "chain" (4 adjacent d indices for fixed b) and
// walks all T timesteps. Loads are staged through a 24-deep per-thread
// cp.async ring in SMEM (each thread consumes only its own slot -> no
// __syncthreads needed; cp.async.wait_group provides ordering).

#ifndef LIF_CTA
#define LIF_CTA 128
#endif
#define LIF_STAGES 24   // 24 * 128 threads * 16B = 49152 B static smem

__global__ void __launch_bounds__(LIF_CTA, 1)
lif_scan_kernel(const float* __restrict__ x,
                const float* __restrict__ v0,
                float* __restrict__ out,
                int T, int N4, int D4)
{
    __shared__ float4 ring[LIF_STAGES][LIF_CTA];

    const int chain = blockIdx.x * LIF_CTA + threadIdx.x;
    if (chain >= N4) return;

    // byte address of this thread's slot in stage 0
    uint32_t slot0 = (uint32_t)__cvta_generic_to_shared(&ring[0][threadIdx.x]);
    const uint32_t stage_bytes = LIF_CTA * 16u;

    const char* gp = (const char*)x + (size_t)chain * 16u;
    const size_t gstride = (size_t)N4 * 16u;   // bytes per timestep

    // ---- prologue: fill STAGES-1 stages ----
    #pragma unroll
    for (int s = 0; s < LIF_STAGES - 1; s++) {
        if (s < T) {
            uint32_t dst = slot0 + (uint32_t)s * stage_bytes;
            asm volatile("cp.async.cg.shared.global [%0], [%1], 16;\n"
                         :: "r"(dst), "l"(gp) : "memory");
            gp += gstride;
        }
        asm volatile("cp.async.commit_group;\n" ::: "memory");
    }

    // initial membrane potential: v0[d] broadcast over batch.
    // chain covers flat floats [4c, 4c+4); d_start = (4c) % D, so the
    // float4 index into v0 is c % (D/4).
    float4 v = ((const float4*)v0)[chain % D4];

    float4* op = out ? (float4*)out + chain : nullptr;

    int wslot = LIF_STAGES - 1;   // stage slot to write next
    int rslot = 0;                // stage slot to read next

    #pragma unroll 4
    for (int t = 0; t < T; t++) {
        // issue load for timestep t + STAGES - 1 (always commit one group
        // per iteration to keep wait_group accounting uniform)
        if (t + LIF_STAGES - 1 < T) {
            uint32_t dst = slot0 + (uint32_t)wslot * stage_bytes;
            asm volatile("cp.async.cg.shared.global [%0], [%1], 16;\n"
                         :: "r"(dst), "l"(gp) : "memory");
            gp += gstride;
        }
        asm volatile("cp.async.commit_group;\n" ::: "memory");
        if (++wslot == LIF_STAGES) wslot = 0;

        // wait until stage t's group has landed (<= STAGES-1 groups pending)
        asm volatile("cp.async.wait_group %0;\n" :: "n"(LIF_STAGES - 1) : "memory");

        float4 xt;
        {
            uint32_t src = slot0 + (uint32_t)rslot * stage_bytes;
            asm volatile("ld.shared.v4.f32 {%0,%1,%2,%3}, [%4];\n"
                         : "=f"(xt.x), "=f"(xt.y), "=f"(xt.z), "=f"(xt.w)
                         : "r"(src));
        }
        if (++rslot == LIF_STAGES) rslot = 0;

        float4 sp;
        v.x = fmaf(0.5f, v.x, xt.x);
        v.y = fmaf(0.5f, v.y, xt.y);
        v.z = fmaf(0.5f, v.z, xt.z);
        v.w = fmaf(0.5f, v.w, xt.w);
        sp.x = (v.x >= 1.0f) ? 1.0f : 0.0f;  v.x = (v.x >= 1.0f) ? 0.0f : v.x;
        sp.y = (v.y >= 1.0f) ? 1.0f : 0.0f;  v.y = (v.y >= 1.0f) ? 0.0f : v.y;
        sp.z = (v.z >= 1.0f) ? 1.0f : 0.0f;  v.z = (v.z >= 1.0f) ? 0.0f : v.z;
        sp.w = (v.w >= 1.0f) ? 1.0f : 0.0f;  v.w = (v.w >= 1.0f) ? 0.0f : v.w;

        *op = sp;
        op += N4;
    }
}

extern "C" void kernel_launch(void* const* d_in, const int* in_sizes, int n_in,
                              void* d_out, int out_size)
{
    const float* x  = (const float*)d_in[0];   // [T, B, D]
    const float* v0 = (const float*)d_in[1];   // [D]
    float* out = (float*)d_out;

    const int T = 512;                 // fixed by problem setup
    const int total = in_sizes[0];     // T*B*D
    const int D = in_sizes[1];
    const int N  = total / T;          // B*D
    const int N4 = N / 4;
    const int D4 = D / 4;

    const int grid = (N4 + LIF_CTA - 1) / LIF_CTA;
    lif_scan_kernel<<<grid, LIF_CTA>>>(x, v0, out, T, N4, D4);
}

// round 2
// speedup vs baseline: 1.0054x; 1.0054x over previous
#include <cuda_runtime.h>
#include <cstdint>

// LIF neuron scan: v = 0.5*v + x_t; spike = (v >= 1); v = spike ? 0 : v
// x: [T, B, D] f32, v0: [D] f32, out spikes: [T, B, D] f32.
// Each thread owns one float4 "chain" (4 adjacent flat indices) and walks all
// T timesteps. Loads are staged through a 24-deep per-thread cp.async ring in
// SMEM (each thread consumes only its own slot -> no __syncthreads;
// cp.async.wait_group alone orders producer/consumer).
//
// R2 change: grid = 148 (one CTA per SM, all SMs active) with ceil-divided
// chains per CTA, instead of 128 CTAs leaving 20 SMs idle.

#ifndef LIF_CTA
#define LIF_CTA 128
#endif
#define LIF_STAGES 24   // 24 * 128 threads * 16B = 49152 B static smem
#define LIF_GRID  148   // one CTA per SM

__global__ void __launch_bounds__(LIF_CTA, 1)
lif_scan_kernel(const float* __restrict__ x,
                const float* __restrict__ v0,
                float* __restrict__ out,
                int T, int N4, int D4, int chunk)
{
    __shared__ float4 ring[LIF_STAGES][LIF_CTA];

    const int chain = blockIdx.x * chunk + threadIdx.x;
    if (threadIdx.x >= chunk || chain >= N4) return;

    // byte address of this thread's slot in stage 0
    uint32_t slot0 = (uint32_t)__cvta_generic_to_shared(&ring[0][threadIdx.x]);
    const uint32_t stage_bytes = LIF_CTA * 16u;

    const char* gp = (const char*)x + (size_t)chain * 16u;
    const size_t gstride = (size_t)N4 * 16u;   // bytes per timestep

    // ---- prologue: fill STAGES-1 stages (T >= STAGES assumed; T=512) ----
    #pragma unroll
    for (int s = 0; s < LIF_STAGES - 1; s++) {
        uint32_t dst = slot0 + (uint32_t)s * stage_bytes;
        asm volatile("cp.async.cg.shared.global [%0], [%1], 16;\n"
                     :: "r"(dst), "l"(gp) : "memory");
        gp += gstride;
        asm volatile("cp.async.commit_group;\n" ::: "memory");
    }

    // initial membrane potential: v0[d] broadcast over batch.
    float4 v = ((const float4*)v0)[chain % D4];

    float4* op = (float4*)out + chain;

    int wslot = LIF_STAGES - 1;   // stage slot to write next
    int rslot = 0;                // stage slot to read next

    const int steady = T - (LIF_STAGES - 1);

    #pragma unroll 4
    for (int t = 0; t < T; t++) {
        // issue load for timestep t + STAGES - 1 (steady phase only); always
        // commit one group per iteration to keep wait_group accounting uniform
        if (t < steady) {
            uint32_t dst = slot0 + (uint32_t)wslot * stage_bytes;
            asm volatile("cp.async.cg.shared.global [%0], [%1], 16;\n"
                         :: "r"(dst), "l"(gp) : "memory");
            gp += gstride;
        }
        asm volatile("cp.async.commit_group;\n" ::: "memory");
        if (++wslot == LIF_STAGES) wslot = 0;

        // wait until stage t's group has landed (<= STAGES-1 groups pending)
        asm volatile("cp.async.wait_group %0;\n" :: "n"(LIF_STAGES - 1) : "memory");

        float4 xt;
        {
            uint32_t src = slot0 + (uint32_t)rslot * stage_bytes;
            asm volatile("ld.shared.v4.f32 {%0,%1,%2,%3}, [%4];\n"
                         : "=f"(xt.x), "=f"(xt.y), "=f"(xt.z), "=f"(xt.w)
                         : "r"(src));
        }
        if (++rslot == LIF_STAGES) rslot = 0;

        float4 sp;
        v.x = fmaf(0.5f, v.x, xt.x);
        v.y = fmaf(0.5f, v.y, xt.y);
        v.z = fmaf(0.5f, v.z, xt.z);
        v.w = fmaf(0.5f, v.w, xt.w);
        sp.x = (v.x >= 1.0f) ? 1.0f : 0.0f;  v.x = (v.x >= 1.0f) ? 0.0f : v.x;
        sp.y = (v.y >= 1.0f) ? 1.0f : 0.0f;  v.y = (v.y >= 1.0f) ? 0.0f : v.y;
        sp.z = (v.z >= 1.0f) ? 1.0f : 0.0f;  v.z = (v.z >= 1.0f) ? 0.0f : v.z;
        sp.w = (v.w >= 1.0f) ? 1.0f : 0.0f;  v.w = (v.w >= 1.0f) ? 0.0f : v.w;

        *op = sp;
        op += N4;
    }
}

extern "C" void kernel_launch(void* const* d_in, const int* in_sizes, int n_in,
                              void* d_out, int out_size)
{
    const float* x  = (const float*)d_in[0];   // [T, B, D]
    const float* v0 = (const float*)d_in[1];   // [D]
    float* out = (float*)d_out;

    const int T = 512;                 // fixed by problem setup
    const int total = in_sizes[0];     // T*B*D
    const int D = in_sizes[1];
    const int N  = total / T;          // B*D
    const int N4 = N / 4;
    const int D4 = D / 4;

    // Spread chains over all 148 SMs; chains per CTA capped at CTA size.
    int chunk = (N4 + LIF_GRID - 1) / LIF_GRID;
    if (chunk > LIF_CTA) chunk = LIF_CTA;
    int grid = (N4 + chunk - 1) / chunk;

    lif_scan_kernel<<<grid, LIF_CTA>>>(x, v0, out, T, N4, D4, chunk);
}